// round 15
// baseline (speedup 1.0000x reference)
#include <cuda_runtime.h>
#include <cuda_bf16.h>

#define N_NODES 50000
#define N_EDGES 800000
#define IN_DIM  64
#define HID_DIM 128
#define OUT_DIM 64
#define CAP     48     // bucket capacity; in-degree ~Poisson(16), P(max>=48)~3e-6

typedef unsigned long long u64;

// ---------------- packed f32x2 helpers (Blackwell FFMA2/FADD2) ----------------
__device__ __forceinline__ u64 pk(float x, float y) {
    u64 r; asm("mov.b64 %0, {%1, %2};" : "=l"(r) : "f"(x), "f"(y)); return r;
}
__device__ __forceinline__ u64 dup2(float x) {
    u64 r; asm("mov.b64 %0, {%1, %2};" : "=l"(r) : "f"(x), "f"(x)); return r;
}
__device__ __forceinline__ void fma2(u64& d, u64 a, u64 b) {
    asm("fma.rn.f32x2 %0, %1, %2, %3;" : "=l"(d) : "l"(a), "l"(b), "l"(d));
}
__device__ __forceinline__ void add2(u64& d, u64 a) {
    asm("add.rn.f32x2 %0, %1, %2;" : "=l"(d) : "l"(d), "l"(a));
}
__device__ __forceinline__ float2 unpk(u64 a) {
    float2 f; asm("mov.b64 {%0, %1}, %2;" : "=f"(f.x), "=f"(f.y) : "l"(a)); return f;
}

// ---------------- scratch ----------------
__device__ __align__(16) float g_zs[N_NODES * IN_DIM];    // dinv_s * z_s
__device__ __align__(16) float g_az[N_NODES * IN_DIM];    // aggregated layer-1 input
__device__ __align__(16) float g_h [N_NODES * HID_DIM];   // relu(az @ W1 + b1)
__device__ __align__(16) float g_hw[N_NODES * OUT_DIM];   // dinv_s * (h @ W2)
__device__ float g_dinv[N_NODES];
__device__ int   g_cnt[N_NODES];          // zero-init; reset by k_agg2 each call
__device__ int   g_esrc[N_NODES * CAP];   // per-dst buckets (9.6 MB)

// ---------------- scatter: count + bucket fill in ONE atomic per edge ----------------
__global__ void k_scatter(const int* __restrict__ ei) {
    int e = blockIdx.x * blockDim.x + threadIdx.x;
    if (e < N_EDGES) {
        int s = ei[e];
        int d = ei[N_EDGES + e];
        int pos = atomicAdd(&g_cnt[d], 1);
        if (pos < CAP) g_esrc[d * CAP + pos] = s;
    }
}

// ---------------- dinv + zscale fused (warp per node) ----------------
__global__ __launch_bounds__(256) void k_dinv_zscale(const float* __restrict__ z) {
    int gw   = (blockIdx.x * blockDim.x + threadIdx.x) >> 5;
    int lane = threadIdx.x & 31;
    if (gw >= N_NODES) return;
    int cnt = __ldg(&g_cnt[gw]);
    float dv = rsqrtf((float)(cnt + 1));       // +1 self-loop
    if (lane == 0) g_dinv[gw] = dv;
    u64 r = 0;
    fma2(r, dup2(dv), ((const u64*)z)[gw * 32 + lane]);
    ((u64*)g_zs)[gw * 32 + lane] = r;
}

// ---------------- gather-accumulate: acc += sum_e row[s_e]  (pure FADD2) ----------------
__device__ __forceinline__ u64 agg_gather(const float* __restrict__ src,
                                          int beg, int end, int lane, u64 acc) {
    int e = beg;
    for (; e + 8 <= end; e += 8) {
        int id[8]; u64 vv[8];
        #pragma unroll
        for (int k = 0; k < 8; k++) id[k] = __ldg(&g_esrc[e + k]);
        #pragma unroll
        for (int k = 0; k < 8; k++) vv[k] = ((const u64*)src)[(unsigned)(id[k] * 32 + lane)];
        #pragma unroll
        for (int k = 0; k < 8; k++) add2(acc, vv[k]);
    }
    for (; e + 4 <= end; e += 4) {
        int id[4]; u64 vv[4];
        #pragma unroll
        for (int k = 0; k < 4; k++) id[k] = __ldg(&g_esrc[e + k]);
        #pragma unroll
        for (int k = 0; k < 4; k++) vv[k] = ((const u64*)src)[(unsigned)(id[k] * 32 + lane)];
        #pragma unroll
        for (int k = 0; k < 4; k++) add2(acc, vv[k]);
    }
    for (; e < end; e++) {
        int s = __ldg(&g_esrc[e]);
        add2(acc, ((const u64*)src)[(unsigned)(s * 32 + lane)]);
    }
    return acc;
}

// ---------------- Aggregation 0: az = dinv_d * (sum zs[s] + zs[d]) ----------------
__global__ __launch_bounds__(256) void k_aggz() {
    int gw   = (blockIdx.x * blockDim.x + threadIdx.x) >> 5;
    int lane = threadIdx.x & 31;
    if (gw >= N_NODES) return;
    float di = g_dinv[gw];
    int deg = __ldg(&g_cnt[gw]); if (deg > CAP) deg = CAP;
    u64 acc = ((const u64*)g_zs)[gw * 32 + lane];
    acc = agg_gather(g_zs, gw * CAP, gw * CAP + deg, lane, acc);
    u64 res = 0;
    fma2(res, dup2(di), acc);
    ((u64*)g_az)[gw * 32 + lane] = res;
}

// ---------------- GEMM 1: h = relu(az @ W1 + b1) ----------------
// block = 32 nodes x 32 cols (quarter of W1 per block). smem 16KB -> 8+ blocks/SM.
// lane owns 1 col; acc u64 = {k-even sum, k-odd sum}; 8 nodes per warp.
#define NT1 1563                         // node tiles of 32 (covers 50016)
__global__ __launch_bounds__(128, 8) void k_gemm1(const float* __restrict__ W1,
                                                  const float* __restrict__ b1) {
    __shared__ u64 sW[32 * 32];                      // [t][col] quarter, 8 KB
    __shared__ __align__(16) float sX[32][IN_DIM];   // 8 KB
    int lane = threadIdx.x & 31;
    int w    = threadIdx.x >> 5;
    int q       = blockIdx.x & 3;                    // column quarter
    int base    = (blockIdx.x >> 2) * 32;            // node base
    int colbase = q * 32;

    for (int idx = threadIdx.x; idx < 32 * 32; idx += 128) {
        int t = idx >> 5, j = idx & 31;
        sW[idx] = pk(W1[(2 * t) * 128 + colbase + j],
                     W1[(2 * t + 1) * 128 + colbase + j]);
    }
    for (int idx = threadIdx.x; idx < 512; idx += 128) {     // 32 nodes x 16 float4
        int n = idx >> 4, r = idx & 15;
        if (base + n < N_NODES)
            ((float4*)sX[n])[r] = ((const float4*)(g_az + (size_t)(base + n) * IN_DIM))[r];
    }
    __syncthreads();

    float bb = __ldg(&b1[colbase + lane]);
    u64 acc[8];
    #pragma unroll
    for (int n = 0; n < 8; n++) acc[n] = pk(bb, 0.f);

    #pragma unroll 4
    for (int t2 = 0; t2 < 16; t2++) {
        u64 wv0 = sW[(2 * t2) * 32 + lane];
        u64 wv1 = sW[(2 * t2 + 1) * 32 + lane];
        #pragma unroll
        for (int n = 0; n < 8; n++) {
            ulonglong2 xx = *(const ulonglong2*)&sX[w * 8 + n][4 * t2];
            fma2(acc[n], xx.x, wv0);
            fma2(acc[n], xx.y, wv1);
        }
    }
    #pragma unroll
    for (int n = 0; n < 8; n++) {
        int node = base + w * 8 + n;
        if (node < N_NODES) {
            float2 f = unpk(acc[n]);
            g_h[(size_t)node * HID_DIM + colbase + lane] = fmaxf(f.x + f.y, 0.f);
        }
    }
}

// ---------------- GEMM 2: hw = dinv * (h @ W2) ----------------
// block = 32 nodes x 32 cols (half of W2 per block), k staged in halves. smem 24KB.
__global__ __launch_bounds__(128, 8) void k_gemm2(const float* __restrict__ W2) {
    __shared__ u64 sW[64 * 32];                      // [t][col] half, 16 KB
    __shared__ __align__(16) float sX[32][64];       // 8 KB (k-half)
    int lane = threadIdx.x & 31;
    int w    = threadIdx.x >> 5;
    int hcol    = blockIdx.x & 1;                    // column half
    int base    = (blockIdx.x >> 1) * 32;            // node base
    int colbase = hcol * 32;

    for (int idx = threadIdx.x; idx < 64 * 32; idx += 128) {
        int t = idx >> 5, j = idx & 31;
        sW[idx] = pk(W2[(2 * t) * 64 + colbase + j],
                     W2[(2 * t + 1) * 64 + colbase + j]);
    }

    u64 acc[8];
    #pragma unroll
    for (int n = 0; n < 8; n++) acc[n] = 0;

    #pragma unroll
    for (int kh = 0; kh < 2; kh++) {
        __syncthreads();                             // kh=0: covers sW too; kh=1: sX reuse
        for (int idx = threadIdx.x; idx < 512; idx += 128) {
            int n = idx >> 4, r = idx & 15;
            if (base + n < N_NODES)
                ((float4*)sX[n])[r] =
                    ((const float4*)(g_h + (size_t)(base + n) * HID_DIM + 64 * kh))[r];
        }
        __syncthreads();
        #pragma unroll 4
        for (int t2 = 0; t2 < 16; t2++) {
            u64 wv0 = sW[(32 * kh + 2 * t2) * 32 + lane];
            u64 wv1 = sW[(32 * kh + 2 * t2 + 1) * 32 + lane];
            #pragma unroll
            for (int n = 0; n < 8; n++) {
                ulonglong2 xx = *(const ulonglong2*)&sX[w * 8 + n][4 * t2];
                fma2(acc[n], xx.x, wv0);
                fma2(acc[n], xx.y, wv1);
            }
        }
    }
    #pragma unroll
    for (int n = 0; n < 8; n++) {
        int node = base + w * 8 + n;
        if (node < N_NODES) {
            float dv = __ldg(&g_dinv[node]);
            float2 f = unpk(acc[n]);
            g_hw[(size_t)node * OUT_DIM + colbase + lane] = dv * (f.x + f.y);
        }
    }
}

// ---------------- Aggregation 2: out = dinv_d * (sum hw[s] + hw[d]) + b2; resets g_cnt ----------------
__global__ __launch_bounds__(256) void k_agg2(const float* __restrict__ b2,
                                              float* __restrict__ out) {
    int gw   = (blockIdx.x * blockDim.x + threadIdx.x) >> 5;
    int lane = threadIdx.x & 31;
    if (gw >= N_NODES) return;
    float di = g_dinv[gw];
    int deg = __ldg(&g_cnt[gw]); if (deg > CAP) deg = CAP;
    u64 acc = ((const u64*)g_hw)[gw * 32 + lane];
    acc = agg_gather(g_hw, gw * CAP, gw * CAP + deg, lane, acc);
    float2 bv = ((const float2*)b2)[lane];
    u64 res = pk(bv.x, bv.y);
    fma2(res, dup2(di), acc);
    ((u64*)out)[gw * 32 + lane] = res;
    if (lane == 0) g_cnt[gw] = 0;           // restore invariant for next replay
}

// ---------------- launch ----------------
extern "C" void kernel_launch(void* const* d_in, const int* in_sizes, int n_in,
                              void* d_out, int out_size) {
    const float* z  = nullptr;
    const int*   ei = nullptr;
    const float* W1 = nullptr;
    const float* W2 = nullptr;
    const float* b1 = nullptr;
    const float* b2 = nullptr;
    for (int i = 0; i < n_in; i++) {
        int n = in_sizes[i];
        if      (n == N_NODES * IN_DIM)  z  = (const float*)d_in[i];
        else if (n == 2 * N_EDGES)       ei = (const int*)d_in[i];
        else if (n == IN_DIM * HID_DIM) { if (!W1) W1 = (const float*)d_in[i]; else W2 = (const float*)d_in[i]; }
        else if (n == HID_DIM)           b1 = (const float*)d_in[i];
        else if (n == OUT_DIM)           b2 = (const float*)d_in[i];
    }
    float* out = (float*)d_out;

    const int gE = (N_EDGES + 255) / 256;
    const int gW = (N_NODES * 32 + 255) / 256;

    k_scatter    <<<gE, 256>>>(ei);
    k_dinv_zscale<<<gW, 256>>>(z);
    k_aggz       <<<gW, 256>>>();
    k_gemm1      <<<NT1 * 4, 128>>>(W1, b1);
    k_gemm2      <<<NT1 * 2, 128>>>(W2);
    k_agg2       <<<gW, 256>>>(b2, out);
}

// round 16
// speedup vs baseline: 1.2165x; 1.2165x over previous
#include <cuda_runtime.h>
#include <cuda_bf16.h>

#define N_NODES 50000
#define N_EDGES 800000
#define IN_DIM  64
#define HID_DIM 128
#define OUT_DIM 64
#define CAP     48     // bucket capacity; in-degree ~Poisson(16), P(max>=48)~3e-6

typedef unsigned long long u64;

// ---------------- packed f32x2 helpers (Blackwell FFMA2/FADD2) ----------------
__device__ __forceinline__ u64 pk(float x, float y) {
    u64 r; asm("mov.b64 %0, {%1, %2};" : "=l"(r) : "f"(x), "f"(y)); return r;
}
__device__ __forceinline__ u64 dup2(float x) {
    u64 r; asm("mov.b64 %0, {%1, %2};" : "=l"(r) : "f"(x), "f"(x)); return r;
}
__device__ __forceinline__ void fma2(u64& d, u64 a, u64 b) {
    asm("fma.rn.f32x2 %0, %1, %2, %3;" : "=l"(d) : "l"(a), "l"(b), "l"(d));
}
__device__ __forceinline__ void add2(u64& d, u64 a) {
    asm("add.rn.f32x2 %0, %1, %2;" : "=l"(d) : "l"(d), "l"(a));
}
__device__ __forceinline__ float2 unpk(u64 a) {
    float2 f; asm("mov.b64 {%0, %1}, %2;" : "=f"(f.x), "=f"(f.y) : "l"(a)); return f;
}

// ---------------- scratch ----------------
__device__ __align__(16) float g_zs[N_NODES * IN_DIM];    // dinv_s * z_s
__device__ __align__(16) float g_az[N_NODES * IN_DIM];    // aggregated layer-1 input
__device__ __align__(16) float g_h [N_NODES * HID_DIM];   // relu(az @ W1 + b1)
__device__ __align__(16) float g_hw[N_NODES * OUT_DIM];   // dinv_s * (h @ W2)
__device__ float g_dinv[N_NODES];
__device__ int   g_cnt[N_NODES];          // zero-init; reset by k_agg2 each call
__device__ int   g_esrc[N_NODES * CAP];   // per-dst buckets (9.6 MB)

// ---------------- scatter: count + bucket fill in ONE atomic per edge ----------------
__global__ void k_scatter(const int* __restrict__ ei) {
    int e = blockIdx.x * blockDim.x + threadIdx.x;
    if (e < N_EDGES) {
        int s = ei[e];
        int d = ei[N_EDGES + e];
        int pos = atomicAdd(&g_cnt[d], 1);
        if (pos < CAP) g_esrc[d * CAP + pos] = s;
    }
}

// ---------------- dinv + zscale fused (warp per node) ----------------
__global__ __launch_bounds__(256) void k_dinv_zscale(const float* __restrict__ z) {
    int gw   = (blockIdx.x * blockDim.x + threadIdx.x) >> 5;
    int lane = threadIdx.x & 31;
    if (gw >= N_NODES) return;
    int cnt = __ldg(&g_cnt[gw]);
    float dv = rsqrtf((float)(cnt + 1));       // +1 self-loop
    if (lane == 0) g_dinv[gw] = dv;
    u64 r = 0;
    fma2(r, dup2(dv), ((const u64*)z)[gw * 32 + lane]);
    ((u64*)g_zs)[gw * 32 + lane] = r;
}

// ---------------- gather-accumulate: acc += sum_e row[s_e]  (pure FADD2) ----------------
__device__ __forceinline__ u64 agg_gather(const float* __restrict__ src,
                                          int beg, int end, int lane, u64 acc) {
    int e = beg;
    for (; e + 8 <= end; e += 8) {
        int id[8]; u64 vv[8];
        #pragma unroll
        for (int k = 0; k < 8; k++) id[k] = __ldg(&g_esrc[e + k]);
        #pragma unroll
        for (int k = 0; k < 8; k++) vv[k] = ((const u64*)src)[(unsigned)(id[k] * 32 + lane)];
        #pragma unroll
        for (int k = 0; k < 8; k++) add2(acc, vv[k]);
    }
    for (; e + 4 <= end; e += 4) {
        int id[4]; u64 vv[4];
        #pragma unroll
        for (int k = 0; k < 4; k++) id[k] = __ldg(&g_esrc[e + k]);
        #pragma unroll
        for (int k = 0; k < 4; k++) vv[k] = ((const u64*)src)[(unsigned)(id[k] * 32 + lane)];
        #pragma unroll
        for (int k = 0; k < 4; k++) add2(acc, vv[k]);
    }
    for (; e < end; e++) {
        int s = __ldg(&g_esrc[e]);
        add2(acc, ((const u64*)src)[(unsigned)(s * 32 + lane)]);
    }
    return acc;
}

// ---------------- Aggregation 0: az = dinv_d * (sum zs[s] + zs[d]) ----------------
__global__ __launch_bounds__(256) void k_aggz() {
    int gw   = (blockIdx.x * blockDim.x + threadIdx.x) >> 5;
    int lane = threadIdx.x & 31;
    if (gw >= N_NODES) return;
    float di = g_dinv[gw];
    int deg = __ldg(&g_cnt[gw]); if (deg > CAP) deg = CAP;
    u64 acc = ((const u64*)g_zs)[gw * 32 + lane];
    acc = agg_gather(g_zs, gw * CAP, gw * CAP + deg, lane, acc);
    u64 res = 0;
    fma2(res, dup2(di), acc);
    ((u64*)g_az)[gw * 32 + lane] = res;
}

// ---------------- GEMM 1: h = relu(az @ W1 + b1) ----------------
// warp-pair column split: warp half h owns 64 cols; ONE 16-node tile per block.
// smem 36KB, 6 blocks/SM; grid 3125 (= 50000/16) keeps all SMs at full residency.
__global__ __launch_bounds__(128, 6) void k_gemm1(const float* __restrict__ W1,
                                                  const float* __restrict__ b1) {
    __shared__ u64 sW[32 * 128];                      // 32 KB
    __shared__ __align__(16) float sX[16][IN_DIM];    // 4 KB
    int lane = threadIdx.x & 31;
    int w    = threadIdx.x >> 5;
    int h    = w & 1;        // column half (0: cols 0-63, 1: cols 64-127)
    int g    = w >> 1;       // node group (0: nodes 0-7, 1: nodes 8-15)
    int base = blockIdx.x * 16;

    for (int idx = threadIdx.x; idx < 32 * 128; idx += 128) {
        int t = idx >> 7, j = idx & 127;
        sW[idx] = pk(W1[(2 * t) * 128 + j], W1[(2 * t + 1) * 128 + j]);
    }
    #pragma unroll
    for (int q = 0; q < 2; q++) {
        int idx = threadIdx.x + 128 * q;              // 0..255 float4s
        int n = idx >> 4, r = idx & 15;
        ((float4*)sX[n])[r] = ((const float4*)(g_az + (size_t)(base + n) * IN_DIM))[r];
    }
    __syncthreads();

    int c = 64 * h + 2 * lane;
    float2 bb = *(const float2*)&b1[c];
    u64 a0[8], a1[8];
    #pragma unroll
    for (int n = 0; n < 8; n++) { a0[n] = pk(bb.x, 0.f); a1[n] = pk(bb.y, 0.f); }
    #pragma unroll 4
    for (int t2 = 0; t2 < 16; t2++) {                 // double k-pair steps
        ulonglong2 wv0 = *(const ulonglong2*)&sW[(2 * t2) * 128 + c];
        ulonglong2 wv1 = *(const ulonglong2*)&sW[(2 * t2 + 1) * 128 + c];
        #pragma unroll
        for (int n = 0; n < 8; n++) {
            ulonglong2 xx = *(const ulonglong2*)&sX[g * 8 + n][4 * t2];  // 16B bcast
            fma2(a0[n], xx.x, wv0.x); fma2(a1[n], xx.x, wv0.y);
            fma2(a0[n], xx.y, wv1.x); fma2(a1[n], xx.y, wv1.y);
        }
    }
    #pragma unroll
    for (int n = 0; n < 8; n++) {
        float2 f0 = unpk(a0[n]), f1 = unpk(a1[n]);
        float* hrow = g_h + (size_t)(base + g * 8 + n) * HID_DIM + 64 * h;
        ((float2*)hrow)[lane] =
            make_float2(fmaxf(f0.x + f0.y, 0.f), fmaxf(f1.x + f1.y, 0.f));
    }
}

// ---------------- GEMM 2: hw = dinv * (h @ W2), 8 nodes/warp, k-halved staging ----------------
// smem 40KB -> 5 blocks/SM
__global__ __launch_bounds__(128, 5) void k_gemm2(const float* __restrict__ W2) {
    __shared__ u64 sW[64 * 64];                        // 32 KB
    __shared__ __align__(16) float sX[4][8][64];       // 8 KB (k half at a time)
    int lane = threadIdx.x & 31;
    int w    = threadIdx.x >> 5;
    for (int idx = threadIdx.x; idx < 64 * 64; idx += 128) {
        int t = idx >> 6, j = idx & 63;
        sW[idx] = pk(W2[(2 * t) * 64 + j], W2[(2 * t + 1) * 64 + j]);
    }
    __syncthreads();
    int c0 = 2 * lane;

    int warpId = blockIdx.x * 4 + w;
    int nWarps = gridDim.x * 4;
    for (int base = warpId * 8; base < N_NODES; base += nWarps * 8) {
        u64 a0[8], a1[8];
        #pragma unroll
        for (int n = 0; n < 8; n++) { a0[n] = 0; a1[n] = 0; }
        #pragma unroll
        for (int kh = 0; kh < 2; kh++) {
            __syncwarp();
            #pragma unroll
            for (int q = 0; q < 4; q++) {
                int idx = lane + 32 * q;               // 0..127 float4s
                int n = idx >> 4, r = idx & 15;
                ((float4*)sX[w][n])[r] =
                    ((const float4*)(g_h + (size_t)(base + n) * HID_DIM + 64 * kh))[r];
            }
            __syncwarp();
            #pragma unroll 4
            for (int t2 = 0; t2 < 16; t2++) {
                int t = 32 * kh + 2 * t2;
                ulonglong2 wv0 = *(const ulonglong2*)&sW[t * 64 + c0];
                ulonglong2 wv1 = *(const ulonglong2*)&sW[(t + 1) * 64 + c0];
                #pragma unroll
                for (int n = 0; n < 8; n++) {
                    ulonglong2 xx = *(const ulonglong2*)&sX[w][n][4 * t2];
                    fma2(a0[n], xx.x, wv0.x); fma2(a1[n], xx.x, wv0.y);
                    fma2(a0[n], xx.y, wv1.x); fma2(a1[n], xx.y, wv1.y);
                }
            }
        }
        #pragma unroll
        for (int n = 0; n < 8; n++) {
            float dv = __ldg(&g_dinv[base + n]);
            float2 f0 = unpk(a0[n]), f1 = unpk(a1[n]);
            ((float2*)(g_hw + (size_t)(base + n) * OUT_DIM))[lane] =
                make_float2(dv * (f0.x + f0.y), dv * (f1.x + f1.y));
        }
        __syncwarp();
    }
}

// ---------------- Aggregation 2: out = dinv_d * (sum hw[s] + hw[d]) + b2; resets g_cnt ----------------
__global__ __launch_bounds__(256) void k_agg2(const float* __restrict__ b2,
                                              float* __restrict__ out) {
    int gw   = (blockIdx.x * blockDim.x + threadIdx.x) >> 5;
    int lane = threadIdx.x & 31;
    if (gw >= N_NODES) return;
    float di = g_dinv[gw];
    int deg = __ldg(&g_cnt[gw]); if (deg > CAP) deg = CAP;
    u64 acc = ((const u64*)g_hw)[gw * 32 + lane];
    acc = agg_gather(g_hw, gw * CAP, gw * CAP + deg, lane, acc);
    float2 bv = ((const float2*)b2)[lane];
    u64 res = pk(bv.x, bv.y);
    fma2(res, dup2(di), acc);
    ((u64*)out)[gw * 32 + lane] = res;
    if (lane == 0) g_cnt[gw] = 0;           // restore invariant for next replay
}

// ---------------- launch ----------------
extern "C" void kernel_launch(void* const* d_in, const int* in_sizes, int n_in,
                              void* d_out, int out_size) {
    const float* z  = nullptr;
    const int*   ei = nullptr;
    const float* W1 = nullptr;
    const float* W2 = nullptr;
    const float* b1 = nullptr;
    const float* b2 = nullptr;
    for (int i = 0; i < n_in; i++) {
        int n = in_sizes[i];
        if      (n == N_NODES * IN_DIM)  z  = (const float*)d_in[i];
        else if (n == 2 * N_EDGES)       ei = (const int*)d_in[i];
        else if (n == IN_DIM * HID_DIM) { if (!W1) W1 = (const float*)d_in[i]; else W2 = (const float*)d_in[i]; }
        else if (n == HID_DIM)           b1 = (const float*)d_in[i];
        else if (n == OUT_DIM)           b2 = (const float*)d_in[i];
    }
    float* out = (float*)d_out;

    const int gE = (N_EDGES + 255) / 256;
    const int gW = (N_NODES * 32 + 255) / 256;

    k_scatter    <<<gE, 256>>>(ei);
    k_dinv_zscale<<<gW, 256>>>(z);
    k_aggz       <<<gW, 256>>>();
    k_gemm1      <<<3125, 128>>>(W1, b1);    // one 16-node tile per block
    k_gemm2      <<<1563, 128>>>(W2);
    k_agg2       <<<gW, 256>>>(b2, out);
}

// round 17
// speedup vs baseline: 1.2420x; 1.0209x over previous
#include <cuda_runtime.h>
#include <cuda_bf16.h>

#define N_NODES 50000
#define N_EDGES 800000
#define IN_DIM  64
#define HID_DIM 128
#define OUT_DIM 64
#define CAP     48     // bucket capacity; in-degree ~Poisson(16), P(max>=48)~3e-6

typedef unsigned long long u64;

// ---------------- packed f32x2 helpers (Blackwell FFMA2/FADD2) ----------------
__device__ __forceinline__ u64 pk(float x, float y) {
    u64 r; asm("mov.b64 %0, {%1, %2};" : "=l"(r) : "f"(x), "f"(y)); return r;
}
__device__ __forceinline__ u64 dup2(float x) {
    u64 r; asm("mov.b64 %0, {%1, %2};" : "=l"(r) : "f"(x), "f"(x)); return r;
}
__device__ __forceinline__ void fma2(u64& d, u64 a, u64 b) {
    asm("fma.rn.f32x2 %0, %1, %2, %3;" : "=l"(d) : "l"(a), "l"(b), "l"(d));
}
__device__ __forceinline__ void add2(u64& d, u64 a) {
    asm("add.rn.f32x2 %0, %1, %2;" : "=l"(d) : "l"(d), "l"(a));
}
__device__ __forceinline__ float2 unpk(u64 a) {
    float2 f; asm("mov.b64 {%0, %1}, %2;" : "=f"(f.x), "=f"(f.y) : "l"(a)); return f;
}

// ---------------- scratch ----------------
__device__ __align__(16) float g_zs[N_NODES * IN_DIM];    // dinv_s * z_s
__device__ __align__(16) float g_az[N_NODES * IN_DIM];    // aggregated layer-1 input
__device__ __align__(16) float g_hw[N_NODES * OUT_DIM];   // dinv_s * (relu(az@W1+b1) @ W2)
__device__ float g_dinv[N_NODES];
__device__ int   g_cnt[N_NODES];          // zero-init; reset by k_agg2 each call
__device__ int   g_esrc[N_NODES * CAP];   // per-dst buckets (9.6 MB)

// ---------------- scatter: count + bucket fill in ONE atomic per edge ----------------
__global__ void k_scatter(const int* __restrict__ ei) {
    int e = blockIdx.x * blockDim.x + threadIdx.x;
    if (e < N_EDGES) {
        int s = ei[e];
        int d = ei[N_EDGES + e];
        int pos = atomicAdd(&g_cnt[d], 1);
        if (pos < CAP) g_esrc[d * CAP + pos] = s;
    }
}

// ---------------- dinv + zscale fused (warp per node) ----------------
__global__ __launch_bounds__(256) void k_dinv_zscale(const float* __restrict__ z) {
    int gw   = (blockIdx.x * blockDim.x + threadIdx.x) >> 5;
    int lane = threadIdx.x & 31;
    if (gw >= N_NODES) return;
    int cnt = __ldg(&g_cnt[gw]);
    float dv = rsqrtf((float)(cnt + 1));       // +1 self-loop
    if (lane == 0) g_dinv[gw] = dv;
    u64 r = 0;
    fma2(r, dup2(dv), ((const u64*)z)[gw * 32 + lane]);
    ((u64*)g_zs)[gw * 32 + lane] = r;
}

// ---------------- gather-accumulate: acc += sum_e row[s_e]  (pure FADD2) ----------------
__device__ __forceinline__ u64 agg_gather(const float* __restrict__ src,
                                          int beg, int end, int lane, u64 acc) {
    int e = beg;
    for (; e + 8 <= end; e += 8) {
        int id[8]; u64 vv[8];
        #pragma unroll
        for (int k = 0; k < 8; k++) id[k] = __ldg(&g_esrc[e + k]);
        #pragma unroll
        for (int k = 0; k < 8; k++) vv[k] = ((const u64*)src)[(unsigned)(id[k] * 32 + lane)];
        #pragma unroll
        for (int k = 0; k < 8; k++) add2(acc, vv[k]);
    }
    for (; e + 4 <= end; e += 4) {
        int id[4]; u64 vv[4];
        #pragma unroll
        for (int k = 0; k < 4; k++) id[k] = __ldg(&g_esrc[e + k]);
        #pragma unroll
        for (int k = 0; k < 4; k++) vv[k] = ((const u64*)src)[(unsigned)(id[k] * 32 + lane)];
        #pragma unroll
        for (int k = 0; k < 4; k++) add2(acc, vv[k]);
    }
    for (; e < end; e++) {
        int s = __ldg(&g_esrc[e]);
        add2(acc, ((const u64*)src)[(unsigned)(s * 32 + lane)]);
    }
    return acc;
}

// ---------------- Aggregation 0: az = dinv_d * (sum zs[s] + zs[d]) ----------------
__global__ __launch_bounds__(256) void k_aggz() {
    int gw   = (blockIdx.x * blockDim.x + threadIdx.x) >> 5;
    int lane = threadIdx.x & 31;
    if (gw >= N_NODES) return;
    float di = g_dinv[gw];
    int deg = __ldg(&g_cnt[gw]); if (deg > CAP) deg = CAP;
    u64 acc = ((const u64*)g_zs)[gw * 32 + lane];
    acc = agg_gather(g_zs, gw * CAP, gw * CAP + deg, lane, acc);
    u64 res = 0;
    fma2(res, dup2(di), acc);
    ((u64*)g_az)[gw * 32 + lane] = res;
}

// ---------------- fused MLP: hw = dinv * (relu(az@W1+b1) @ W2) ----------------
// 256 threads (8 warps x 8 nodes = 64 nodes/block); smem 112KB -> 2 blocks/SM = 16 warps/SM.
__global__ __launch_bounds__(256, 2) void k_mlp(const float* __restrict__ W1,
                                                const float* __restrict__ b1,
                                                const float* __restrict__ W2) {
    extern __shared__ __align__(16) char smem[];
    u64*   sW1 = (u64*)smem;                   // [32][128]  32 KB
    u64*   sW2 = sW1 + 32 * 128;               // [64][64]   32 KB
    float* sH  = (float*)(sW2 + 64 * 64);      // [8][8][HID_DIM]  32 KB
    float* sX  = sH + 8 * 8 * HID_DIM;         // [8][8][IN_DIM]   16 KB

    int lane = threadIdx.x & 31;
    int w    = threadIdx.x >> 5;               // 0..7
    for (int idx = threadIdx.x; idx < 32 * 128; idx += 256) {
        int t = idx >> 7, j = idx & 127;
        sW1[idx] = pk(W1[(2 * t) * 128 + j], W1[(2 * t + 1) * 128 + j]);
    }
    for (int idx = threadIdx.x; idx < 64 * 64; idx += 256) {
        int t = idx >> 6, j = idx & 63;
        sW2[idx] = pk(W2[(2 * t) * 64 + j], W2[(2 * t + 1) * 64 + j]);
    }
    __syncthreads();

    int c0 = 2 * lane;
    float2 bA = *(const float2*)&b1[c0];
    float2 bB = *(const float2*)&b1[c0 + 64];
    float* myH = sH + w * 8 * HID_DIM;
    float* myX = sX + w * 8 * IN_DIM;

    int warpId = blockIdx.x * 8 + w;
    int nWarps = gridDim.x * 8;
    for (int base = warpId * 8; base < N_NODES; base += nWarps * 8) {
        // stage 8 nodes of az (8 x 256B)
        #pragma unroll
        for (int q = 0; q < 4; q++) {
            int idx = lane + 32 * q;
            int n = idx >> 4, r = idx & 15;
            ((float4*)(myX + n * IN_DIM))[r] =
                ((const float4*)(g_az + (size_t)(base + n) * IN_DIM))[r];
        }
        __syncwarp();

        // layer 1: h = relu(az @ W1 + b1) -> smem
        {
            u64 aA0[8], aA1[8], aB0[8], aB1[8];
            #pragma unroll
            for (int n = 0; n < 8; n++) {
                aA0[n] = pk(bA.x, 0.f); aA1[n] = pk(bA.y, 0.f);
                aB0[n] = pk(bB.x, 0.f); aB1[n] = pk(bB.y, 0.f);
            }
            #pragma unroll 4
            for (int t = 0; t < 32; t++) {
                ulonglong2 wA = *(const ulonglong2*)&sW1[t * 128 + c0];
                ulonglong2 wB = *(const ulonglong2*)&sW1[t * 128 + c0 + 64];
                #pragma unroll
                for (int n = 0; n < 8; n++) {
                    u64 xp = *(const u64*)&myX[n * IN_DIM + 2 * t];
                    fma2(aA0[n], xp, wA.x); fma2(aA1[n], xp, wA.y);
                    fma2(aB0[n], xp, wB.x); fma2(aB1[n], xp, wB.y);
                }
            }
            #pragma unroll
            for (int n = 0; n < 8; n++) {
                float2 f0 = unpk(aA0[n]), f1 = unpk(aA1[n]);
                float2 f2 = unpk(aB0[n]), f3 = unpk(aB1[n]);
                float* hrow = myH + n * HID_DIM;
                ((float2*)hrow)[lane] =
                    make_float2(fmaxf(f0.x + f0.y, 0.f), fmaxf(f1.x + f1.y, 0.f));
                ((float2*)(hrow + 64))[lane] =
                    make_float2(fmaxf(f2.x + f2.y, 0.f), fmaxf(f3.x + f3.y, 0.f));
            }
        }
        __syncwarp();

        // layer 2: hw = dinv * (h @ W2) -> global
        {
            u64 a0[8], a1[8];
            #pragma unroll
            for (int n = 0; n < 8; n++) { a0[n] = 0; a1[n] = 0; }
            #pragma unroll 8
            for (int t = 0; t < 64; t++) {
                ulonglong2 wA = *(const ulonglong2*)&sW2[t * 64 + c0];
                #pragma unroll
                for (int n = 0; n < 8; n++) {
                    u64 xp = *(const u64*)&myH[n * HID_DIM + 2 * t];
                    fma2(a0[n], xp, wA.x); fma2(a1[n], xp, wA.y);
                }
            }
            #pragma unroll
            for (int n = 0; n < 8; n++) {
                float dv = __ldg(&g_dinv[base + n]);
                float2 f0 = unpk(a0[n]), f1 = unpk(a1[n]);
                ((float2*)(g_hw + (size_t)(base + n) * OUT_DIM))[lane] =
                    make_float2(dv * (f0.x + f0.y), dv * (f1.x + f1.y));
            }
        }
        __syncwarp();
    }
}

// ---------------- Aggregation 2: out = dinv_d * (sum hw[s] + hw[d]) + b2; resets g_cnt ----------------
__global__ __launch_bounds__(256) void k_agg2(const float* __restrict__ b2,
                                              float* __restrict__ out) {
    int gw   = (blockIdx.x * blockDim.x + threadIdx.x) >> 5;
    int lane = threadIdx.x & 31;
    if (gw >= N_NODES) return;
    float di = g_dinv[gw];
    int deg = __ldg(&g_cnt[gw]); if (deg > CAP) deg = CAP;
    u64 acc = ((const u64*)g_hw)[gw * 32 + lane];
    acc = agg_gather(g_hw, gw * CAP, gw * CAP + deg, lane, acc);
    float2 bv = ((const float2*)b2)[lane];
    u64 res = pk(bv.x, bv.y);
    fma2(res, dup2(di), acc);
    ((u64*)out)[gw * 32 + lane] = res;
    if (lane == 0) g_cnt[gw] = 0;           // restore invariant for next replay
}

// ---------------- launch ----------------
extern "C" void kernel_launch(void* const* d_in, const int* in_sizes, int n_in,
                              void* d_out, int out_size) {
    const float* z  = nullptr;
    const int*   ei = nullptr;
    const float* W1 = nullptr;
    const float* W2 = nullptr;
    const float* b1 = nullptr;
    const float* b2 = nullptr;
    for (int i = 0; i < n_in; i++) {
        int n = in_sizes[i];
        if      (n == N_NODES * IN_DIM)  z  = (const float*)d_in[i];
        else if (n == 2 * N_EDGES)       ei = (const int*)d_in[i];
        else if (n == IN_DIM * HID_DIM) { if (!W1) W1 = (const float*)d_in[i]; else W2 = (const float*)d_in[i]; }
        else if (n == HID_DIM)           b1 = (const float*)d_in[i];
        else if (n == OUT_DIM)           b2 = (const float*)d_in[i];
    }
    float* out = (float*)d_out;

    const int MLP_SMEM = 32 * 128 * 8 + 64 * 64 * 8 + 8 * 8 * HID_DIM * 4 + 8 * 8 * IN_DIM * 4; // 114688
    static bool attr_set = false;
    if (!attr_set) {
        cudaFuncSetAttribute(k_mlp, cudaFuncAttributeMaxDynamicSharedMemorySize, MLP_SMEM);
        attr_set = true;
    }

    const int gE = (N_EDGES + 255) / 256;
    const int gW = (N_NODES * 32 + 255) / 256;
    const int gM = 782;    // 8 warps x 8 nodes = 64 nodes/block; covers 50048 with loop guard

    k_scatter    <<<gE, 256>>>(ei);
    k_dinv_zscale<<<gW, 256>>>(z);
    k_aggz       <<<gW, 256>>>();
    k_mlp        <<<gM, 256, MLP_SMEM>>>(W1, b1, W2);
    k_agg2       <<<gW, 256>>>(b2, out);
}